// round 16
// baseline (speedup 1.0000x reference)
#include <cuda_runtime.h>
#include <cstdint>

// ProbAttention (Informer ProbSparse) — B=2, L=4096, H=8, D=64, FACTOR=5 → u=U_part=45

#define BB 2
#define LL 4096
#define HH 8
#define DD 64
#define NBH 16          // B*H
#define UU 45
#define UP 48           // padded u
#define NSPLIT 32
#define KPB (LL / NSPLIT)   // 128 keys per block
#define TIL 64
#define NTILE (KPB / TIL)   // 2
#define NSAMP (LL * UU)     // 184320
#define CANDCAP 1024

__device__ float g_M[NBH * LL];
__device__ int   g_Mtop[NBH * UU];
__device__ float g_pm[NBH * NSPLIT * UP];
__device__ float g_pl[NBH * NSPLIT * UP];
__device__ float g_pacc[NBH * NSPLIT * UP * DD];

// ---------------------------------------------------------------- threefry
__device__ __forceinline__ uint32_t rotl32(uint32_t x, int n) {
    return (x << n) | (x >> (32 - n));
}

__device__ __forceinline__ void threefry2x32(uint32_t k0, uint32_t k1,
                                             uint32_t c0, uint32_t c1,
                                             uint32_t& o0, uint32_t& o1) {
    uint32_t ks0 = k0, ks1 = k1, ks2 = k0 ^ k1 ^ 0x1BD11BDAu;
    uint32_t x0 = c0 + ks0, x1 = c1 + ks1;
#define TF_R(r) { x0 += x1; x1 = rotl32(x1, r); x1 ^= x0; }
    TF_R(13) TF_R(15) TF_R(26) TF_R(6)
    x0 += ks1; x1 += ks2 + 1u;
    TF_R(17) TF_R(29) TF_R(16) TF_R(24)
    x0 += ks2; x1 += ks0 + 2u;
    TF_R(13) TF_R(15) TF_R(26) TF_R(6)
    x0 += ks0; x1 += ks1 + 3u;
    TF_R(17) TF_R(29) TF_R(16) TF_R(24)
    x0 += ks1; x1 += ks2 + 4u;
    TF_R(13) TF_R(15) TF_R(26) TF_R(6)
    x0 += ks2; x1 += ks0 + 5u;
#undef TF_R
    o0 = x0; o1 = x1;
}

// Modern JAX partitionable threefry (verified round 3):
//   k2 = threefry((0,1),(0,1)); bits[j] = xor-fold of threefry(k2,(0,j));
//   idx[q,s] = bits[q*45+s] & 4095.
__device__ __forceinline__ int sample_idx(int q, int s) {
    uint32_t s0, s1;
    threefry2x32(0u, 1u, 0u, 1u, s0, s1);      // constant-folded by ptxas
    uint32_t o0, o1;
    threefry2x32(s0, s1, 0u, (uint32_t)(q * UU + s), o0, o1);
    return (int)((o0 ^ o1) & 4095u);
}

// ---------------------------------------------------------------- sparse measure M
// one warp per (b,h,q); 4 groups of 8 lanes; 6 samples per group per iter.
// Sample indices register-resident (SHFL gather) — no smem in the hot loop.
__global__ __launch_bounds__(256) void m_kernel(const float* __restrict__ Q,
                                                const float* __restrict__ K) {
    int warp = threadIdx.x >> 5;
    int lane = threadIdx.x & 31;
    int w  = blockIdx.x * 8 + warp;
    int bh = w >> 12;
    int q  = w & 4095;
    int b = bh >> 3, h = bh & 7;
    int g = lane >> 3, l8 = lane & 7;

    // each lane computes up to 2 of the 45 indices, then SHFL-gathers its group's 12
    int v1 = sample_idx(q, lane < UU ? lane : 0);
    int v2 = sample_idx(q, (lane + 32) < UU ? (lane + 32) : 0);
    int idxr[12];
#pragma unroll
    for (int k = 0; k < 12; ++k) {
        int s = 4 * k + g;
        int lo = __shfl_sync(0xffffffffu, v1, s & 31);
        int hi = __shfl_sync(0xffffffffu, v2, (s - 32) & 31);
        idxr[k] = (s < 32) ? lo : hi;
    }

    const float* qp = Q + ((size_t)(b * LL + q) * HH + h) * DD + l8 * 8;
    float4 qa = *(const float4*)qp;
    float4 qb = *(const float4*)(qp + 4);
    const float* kbase = K + ((size_t)(b * LL) * HH + h) * DD + l8 * 8;

    float mx = -3.4e38f, sm = 0.f;
    // 2 iters x 4 groups x 6 samples = 48 slots >= 45
#pragma unroll 1
    for (int t = 0; t < 2; ++t) {
        float4 ka[6], kb[6];
        bool vv[6];
#pragma unroll
        for (int k = 0; k < 6; ++k) {
            int s = t * 24 + k * 4 + g;
            vv[k] = (s < UU);
            int i = idxr[t * 6 + k];
            const float* kp = kbase + (size_t)i * (HH * DD);
            ka[k] = *(const float4*)kp;
            kb[k] = *(const float4*)(kp + 4);
        }
        float p[6];
#pragma unroll
        for (int k = 0; k < 6; ++k)
            p[k] = qa.x * ka[k].x + qa.y * ka[k].y + qa.z * ka[k].z + qa.w * ka[k].w
                 + qb.x * kb[k].x + qb.y * kb[k].y + qb.z * kb[k].z + qb.w * kb[k].w;
#pragma unroll
        for (int k = 0; k < 6; ++k) p[k] += __shfl_xor_sync(0xffffffffu, p[k], 1);
#pragma unroll
        for (int k = 0; k < 6; ++k) p[k] += __shfl_xor_sync(0xffffffffu, p[k], 2);
#pragma unroll
        for (int k = 0; k < 6; ++k) p[k] += __shfl_xor_sync(0xffffffffu, p[k], 4);
#pragma unroll
        for (int k = 0; k < 6; ++k)
            if (vv[k]) { mx = fmaxf(mx, p[k]); sm += p[k]; }
    }
    mx = fmaxf(mx, __shfl_xor_sync(0xffffffffu, mx, 8));
    sm +=           __shfl_xor_sync(0xffffffffu, sm, 8);
    mx = fmaxf(mx, __shfl_xor_sync(0xffffffffu, mx, 16));
    sm +=           __shfl_xor_sync(0xffffffffu, sm, 16);
    if (lane == 0) g_M[bh * LL + q] = mx - sm * (1.0f / LL);
}

// ---------------------------------------------------------------- top-45 via radix select + rank sort
// 1024 threads per (b,h). key = (ord(float) << 12) | (4095 - q): unique, value-desc / index-asc.
__global__ __launch_bounds__(1024) void topk_kernel() {
    __shared__ int hist[4096];
    __shared__ int wsum[32];
    __shared__ unsigned long long candk[CANDCAP];
    __shared__ int s_bin, s_nhi, s_cnt, s_bin2;
    int bh = blockIdx.x;
    int t = threadIdx.x;
    int lane = t & 31, warp = t >> 5;

    uint32_t u[4];
#pragma unroll
    for (int j = 0; j < 4; ++j) {
        uint32_t bits = __float_as_uint(g_M[bh * LL + t * 4 + j]);
        u[j] = (bits & 0x80000000u) ? ~bits : (bits | 0x80000000u);
    }
#pragma unroll
    for (int j = 0; j < 4; ++j) hist[t * 4 + j] = 0;
    if (t == 0) s_cnt = 0;
    __syncthreads();
#pragma unroll
    for (int j = 0; j < 4; ++j) atomicAdd(&hist[u[j] >> 20], 1);
    __syncthreads();

    {
        int h[4], c = 0;
#pragma unroll
        for (int j = 0; j < 4; ++j) { h[j] = hist[4095 - (t * 4 + j)]; c += h[j]; }
        int inc = c;
#pragma unroll
        for (int off = 1; off < 32; off <<= 1) {
            int v = __shfl_up_sync(0xffffffffu, inc, off);
            if (lane >= off) inc += v;
        }
        if (lane == 31) wsum[warp] = inc;
        __syncthreads();
        if (warp == 0) {
            int v = wsum[lane], iv = v;
#pragma unroll
            for (int off = 1; off < 32; off <<= 1) {
                int x = __shfl_up_sync(0xffffffffu, iv, off);
                if (lane >= off) iv += x;
            }
            wsum[lane] = iv - v;
        }
        __syncthreads();
        int run = wsum[warp] + (inc - c);
#pragma unroll
        for (int j = 0; j < 4; ++j) {
            int excl = run; run += h[j];
            if (excl < UU && run >= UU) { s_bin = 4095 - (t * 4 + j); s_nhi = excl; }
        }
    }
    __syncthreads();
    int B = s_bin;
    int nhi = s_nhi;
    int cntB = hist[B];
    bool lvl2 = (nhi + cntB > CANDCAP);

    unsigned long long key[4];
#pragma unroll
    for (int j = 0; j < 4; ++j)
        key[j] = ((unsigned long long)u[j] << 12) | (unsigned long long)(4095 - (t * 4 + j));

    if (!lvl2) {
#pragma unroll
        for (int j = 0; j < 4; ++j) {
            if ((int)(u[j] >> 20) >= B) {
                int pos = atomicAdd(&s_cnt, 1);
                if (pos < CANDCAP) candk[pos] = key[j];
            }
        }
    } else {
        __syncthreads();
#pragma unroll
        for (int j = 0; j < 4; ++j) hist[t * 4 + j] = 0;
        __syncthreads();
#pragma unroll
        for (int j = 0; j < 4; ++j)
            if ((int)(u[j] >> 20) == B) atomicAdd(&hist[(u[j] >> 8) & 0xfff], 1);
        __syncthreads();
        int r2 = UU - nhi;
        {
            int h[4], c = 0;
#pragma unroll
            for (int j = 0; j < 4; ++j) { h[j] = hist[4095 - (t * 4 + j)]; c += h[j]; }
            int inc = c;
#pragma unroll
            for (int off = 1; off < 32; off <<= 1) {
                int v = __shfl_up_sync(0xffffffffu, inc, off);
                if (lane >= off) inc += v;
            }
            if (lane == 31) wsum[warp] = inc;
            __syncthreads();
            if (warp == 0) {
                int v = wsum[lane], iv = v;
#pragma unroll
                for (int off = 1; off < 32; off <<= 1) {
                    int x = __shfl_up_sync(0xffffffffu, iv, off);
                    if (lane >= off) iv += x;
                }
                wsum[lane] = iv - v;
            }
            __syncthreads();
            int run = wsum[warp] + (inc - c);
#pragma unroll
            for (int j = 0; j < 4; ++j) {
                int excl = run; run += h[j];
                if (excl < r2 && run >= r2) s_bin2 = 4095 - (t * 4 + j);
            }
        }
        __syncthreads();
        int B2 = s_bin2;
#pragma unroll
        for (int j = 0; j < 4; ++j) {
            int bin = (int)(u[j] >> 20);
            int sub = (int)((u[j] >> 8) & 0xfff);
            if (bin > B || (bin == B && sub >= B2)) {
                int pos = atomicAdd(&s_cnt, 1);
                if (pos < CANDCAP) candk[pos] = key[j];
            }
        }
    }
    __syncthreads();

    int n = s_cnt < CANDCAP ? s_cnt : CANDCAP;
    if (t < n) {
        unsigned long long my = candk[t];
        int rank = 0;
        for (int j = 0; j < n; ++j) rank += (candk[j] > my);
        if (rank < UU) g_Mtop[bh * UU + rank] = 4095 - (int)(my & 0xfffull);
    }
}

// ---------------------------------------------------------------- split-K flash attention (64-wide tile)
// 256 thr = 16x16; thread owns 3 u-rows x (4 keys | 4 dims).
// Softmax fully in registers: each u-row's 64 scores live in one half-warp
// (tx = lane&15), so row max/sum = 4 XOR-shuffles; row state (m,l,alpha) is
// replicated per thread. Scores hit smem once (already exp'd). 3 barriers/tile.
#define ASTR 68
#define SM_QS 0
#define SM_KS (SM_QS + UP * ASTR)
#define SM_VS (SM_KS + TIL * ASTR)
#define SM_SS (SM_VS + TIL * ASTR)
#define SM_TOT (SM_SS + UP * ASTR)

__global__ __launch_bounds__(256) void attn_kernel(const float* __restrict__ Q,
                                                   const float* __restrict__ K,
                                                   const float* __restrict__ V,
                                                   const int*   __restrict__ amask) {
    extern __shared__ float sm_[];
    float* Qs = sm_ + SM_QS;
    float* Ks = sm_ + SM_KS;
    float* Vs = sm_ + SM_VS;
    float* Ss = sm_ + SM_SS;

    int bh = blockIdx.x / NSPLIT;
    int sp = blockIdx.x % NSPLIT;
    int b = bh >> 3, h = bh & 7;
    int t = threadIdx.x;
    int tx = t & 15, ty = t >> 4;
    int u0 = ty * 3;

    for (int i = t; i < UP * DD; i += 256) {
        int u = i >> 6, d = i & 63;
        float v = 0.f;
        if (u < UU) {
            int qi = g_Mtop[bh * UU + u];
            v = Q[((size_t)(b * LL + qi) * HH + h) * DD + d] * 0.125f;  // 1/sqrt(64)
        }
        Qs[u * ASTR + d] = v;
    }

    float mrow[3], lrow[3];
#pragma unroll
    for (int uu = 0; uu < 3; ++uu) { mrow[uu] = -1e30f; lrow[uu] = 0.f; }

    float4 acc[3];
    acc[0] = make_float4(0.f, 0.f, 0.f, 0.f);
    acc[1] = acc[0]; acc[2] = acc[0];
    __syncthreads();

    int j0base = sp * KPB;
#pragma unroll 1
    for (int tile = 0; tile < NTILE; ++tile) {
        int j0 = j0base + tile * TIL;
        {
            const float* kb = K + ((size_t)(b * LL + j0) * HH + h) * DD;
            const float* vb = V + ((size_t)(b * LL + j0) * HH + h) * DD;
#pragma unroll
            for (int r = 0; r < 4; ++r) {
                int idx = t + 256 * r;     // 0..1023 float4s of a 64x64 tile
                int j = idx >> 4, c4 = idx & 15;
                *(float4*)&Ks[j * ASTR + c4 * 4] = *(const float4*)(kb + (size_t)j * (HH * DD) + c4 * 4);
                *(float4*)&Vs[j * ASTR + c4 * 4] = *(const float4*)(vb + (size_t)j * (HH * DD) + c4 * 4);
            }
        }
        __syncthreads();

        // scores: 3u x 4j per thread (j = tx + 16*jj)
        float s[3][4] = {};
#pragma unroll
        for (int d4 = 0; d4 < 16; ++d4) {
            float4 kv[4];
#pragma unroll
            for (int jj = 0; jj < 4; ++jj)
                kv[jj] = *(const float4*)&Ks[(tx + 16 * jj) * ASTR + d4 * 4];
#pragma unroll
            for (int uu = 0; uu < 3; ++uu) {
                float4 qv = *(const float4*)&Qs[(u0 + uu) * ASTR + d4 * 4];
#pragma unroll
                for (int jj = 0; jj < 4; ++jj)
                    s[uu][jj] += qv.x * kv[jj].x + qv.y * kv[jj].y
                               + qv.z * kv[jj].z + qv.w * kv[jj].w;
            }
        }

        int mk[4];
#pragma unroll
        for (int jj = 0; jj < 4; ++jj) mk[jj] = amask[b * LL + j0 + tx + 16 * jj];

        // in-register online softmax (row = half-warp; offsets 1,2,4,8 stay in-half)
        float alpha[3];
#pragma unroll
        for (int uu = 0; uu < 3; ++uu) {
            float cm = -1e30f;
#pragma unroll
            for (int jj = 0; jj < 4; ++jj) {
                s[uu][jj] = mk[jj] ? s[uu][jj] : -1e30f;
                cm = fmaxf(cm, s[uu][jj]);
            }
#pragma unroll
            for (int off = 1; off < 16; off <<= 1)
                cm = fmaxf(cm, __shfl_xor_sync(0xffffffffu, cm, off));
            float mnew = fmaxf(cm, mrow[uu]);
            alpha[uu] = __expf(mrow[uu] - mnew);
            float ls = 0.f;
#pragma unroll
            for (int jj = 0; jj < 4; ++jj) {
                float e = __expf(s[uu][jj] - mnew);
                Ss[(u0 + uu) * ASTR + tx + 16 * jj] = e;
                ls += e;
            }
#pragma unroll
            for (int off = 1; off < 16; off <<= 1)
                ls += __shfl_xor_sync(0xffffffffu, ls, off);
            lrow[uu] = lrow[uu] * alpha[uu] + ls;
            mrow[uu] = mnew;
        }
        __syncthreads();

        // rescale + P@V: thread owns (3u, d=4*tx..4*tx+3)
#pragma unroll
        for (int uu = 0; uu < 3; ++uu) {
            float a = alpha[uu];
            acc[uu].x *= a; acc[uu].y *= a; acc[uu].z *= a; acc[uu].w *= a;
        }
#pragma unroll
        for (int j4 = 0; j4 < TIL / 4; ++j4) {
            float4 vr0 = *(const float4*)&Vs[(j4 * 4 + 0) * ASTR + tx * 4];
            float4 vr1 = *(const float4*)&Vs[(j4 * 4 + 1) * ASTR + tx * 4];
            float4 vr2 = *(const float4*)&Vs[(j4 * 4 + 2) * ASTR + tx * 4];
            float4 vr3 = *(const float4*)&Vs[(j4 * 4 + 3) * ASTR + tx * 4];
#pragma unroll
            for (int uu = 0; uu < 3; ++uu) {
                float4 sv = *(const float4*)&Ss[(u0 + uu) * ASTR + j4 * 4];
                acc[uu].x += sv.x * vr0.x + sv.y * vr1.x + sv.z * vr2.x + sv.w * vr3.x;
                acc[uu].y += sv.x * vr0.y + sv.y * vr1.y + sv.z * vr2.y + sv.w * vr3.y;
                acc[uu].z += sv.x * vr0.z + sv.y * vr1.z + sv.z * vr2.z + sv.w * vr3.z;
                acc[uu].w += sv.x * vr0.w + sv.y * vr1.w + sv.z * vr2.w + sv.w * vr3.w;
            }
        }
        __syncthreads();
    }

    size_t base = (size_t)(bh * NSPLIT + sp) * UP;
#pragma unroll
    for (int uu = 0; uu < 3; ++uu)
        *(float4*)&g_pacc[(base + u0 + uu) * DD + tx * 4] = acc[uu];
    if (tx == 0) {
#pragma unroll
        for (int uu = 0; uu < 3; ++uu) {
            g_pm[base + u0 + uu] = mrow[uu];
            g_pl[base + u0 + uu] = lrow[uu];
        }
    }
}

// ---------------------------------------------------------------- combine split-K partials
// block per (bh,u): 8 warps x 4 splits each, smem tree reduce.
__global__ __launch_bounds__(256) void combine_kernel(float* __restrict__ out) {
    __shared__ float s_wgt[NSPLIT];
    __shared__ float s_acc[8][DD];
    __shared__ float s_inv;
    int bh = blockIdx.x / UU, u = blockIdx.x % UU;
    int b = bh >> 3, h = bh & 7;
    int t = threadIdx.x;
    int warp = t >> 5, lane = t & 31;

    if (t < NSPLIT) s_wgt[t] = g_pm[(bh * NSPLIT + t) * UP + u];
    __syncthreads();

    if (warp == 0) {
        float mv = s_wgt[lane];
        float m = mv;
#pragma unroll
        for (int off = 16; off > 0; off >>= 1) m = fmaxf(m, __shfl_xor_sync(0xffffffffu, m, off));
        float wgt = __expf(mv - m);
        float ls = g_pl[(bh * NSPLIT + lane) * UP + u] * wgt;
#pragma unroll
        for (int off = 16; off > 0; off >>= 1) ls += __shfl_xor_sync(0xffffffffu, ls, off);
        s_wgt[lane] = wgt;
        if (lane == 0) s_inv = 1.0f / ls;
    }
    __syncthreads();

    float o0 = 0.f, o1 = 0.f;
#pragma unroll
    for (int k = 0; k < NSPLIT / 8; ++k) {
        int sp = warp * (NSPLIT / 8) + k;
        size_t pb = ((size_t)(bh * NSPLIT + sp) * UP + u) * DD;
        float wgt = s_wgt[sp];
        o0 += g_pacc[pb + lane] * wgt;
        o1 += g_pacc[pb + lane + 32] * wgt;
    }
    s_acc[warp][lane] = o0;
    s_acc[warp][lane + 32] = o1;
    __syncthreads();

    if (t < DD) {
        float s = 0.f;
#pragma unroll
        for (int w8 = 0; w8 < 8; ++w8) s += s_acc[w8][t];
        size_t ob = ((size_t)(b * UU + u) * HH + h) * DD;
        out[ob + t] = s * s_inv;
    }
}

// ----------------------------------------------------------------
extern "C" void kernel_launch(void* const* d_in, const int* in_sizes, int n_in,
                              void* d_out, int out_size) {
    const float* Q    = (const float*)d_in[0];
    const float* K    = (const float*)d_in[1];
    const float* V    = (const float*)d_in[2];
    const int*   mask = (const int*)d_in[3];
    float* out = (float*)d_out;

    const int attn_smem = SM_TOT * 4;
    cudaFuncSetAttribute(attn_kernel, cudaFuncAttributeMaxDynamicSharedMemorySize, attn_smem);

    m_kernel<<<NBH * LL / 8, 256>>>(Q, K);
    topk_kernel<<<NBH, 1024>>>();
    attn_kernel<<<NBH * NSPLIT, 256, attn_smem>>>(Q, K, V, mask);
    combine_kernel<<<NBH * UU, 256>>>(out);
}

// round 17
// speedup vs baseline: 1.2797x; 1.2797x over previous
#include <cuda_runtime.h>
#include <cstdint>

// ProbAttention (Informer ProbSparse) — B=2, L=4096, H=8, D=64, FACTOR=5 → u=U_part=45

#define BB 2
#define LL 4096
#define HH 8
#define DD 64
#define NBH 16          // B*H
#define UU 45
#define UP 48           // padded u
#define NSPLIT 32
#define KPB (LL / NSPLIT)   // 128 keys per block
#define TIL 64
#define NTILE (KPB / TIL)   // 2
#define NSAMP (LL * UU)     // 184320
#define CANDCAP 1024

__device__ float g_M[NBH * LL];
__device__ int   g_Mtop[NBH * UU];
__device__ float g_pm[NBH * NSPLIT * UP];
__device__ float g_pl[NBH * NSPLIT * UP];
__device__ float g_pacc[NBH * NSPLIT * UP * DD];

// ---------------------------------------------------------------- threefry
__device__ __forceinline__ uint32_t rotl32(uint32_t x, int n) {
    return (x << n) | (x >> (32 - n));
}

__device__ __forceinline__ void threefry2x32(uint32_t k0, uint32_t k1,
                                             uint32_t c0, uint32_t c1,
                                             uint32_t& o0, uint32_t& o1) {
    uint32_t ks0 = k0, ks1 = k1, ks2 = k0 ^ k1 ^ 0x1BD11BDAu;
    uint32_t x0 = c0 + ks0, x1 = c1 + ks1;
#define TF_R(r) { x0 += x1; x1 = rotl32(x1, r); x1 ^= x0; }
    TF_R(13) TF_R(15) TF_R(26) TF_R(6)
    x0 += ks1; x1 += ks2 + 1u;
    TF_R(17) TF_R(29) TF_R(16) TF_R(24)
    x0 += ks2; x1 += ks0 + 2u;
    TF_R(13) TF_R(15) TF_R(26) TF_R(6)
    x0 += ks0; x1 += ks1 + 3u;
    TF_R(17) TF_R(29) TF_R(16) TF_R(24)
    x0 += ks1; x1 += ks2 + 4u;
    TF_R(13) TF_R(15) TF_R(26) TF_R(6)
    x0 += ks2; x1 += ks0 + 5u;
#undef TF_R
    o0 = x0; o1 = x1;
}

// Modern JAX partitionable threefry (verified round 3):
//   k2 = threefry((0,1),(0,1)); bits[j] = xor-fold of threefry(k2,(0,j));
//   idx[q,s] = bits[q*45+s] & 4095.
__device__ __forceinline__ int sample_idx(int q, int s) {
    uint32_t s0, s1;
    threefry2x32(0u, 1u, 0u, 1u, s0, s1);      // constant-folded by ptxas
    uint32_t o0, o1;
    threefry2x32(s0, s1, 0u, (uint32_t)(q * UU + s), o0, o1);
    return (int)((o0 ^ o1) & 4095u);
}

// ---------------------------------------------------------------- sparse measure M (idx folded in)
// one warp per (b,h,q); 4 groups of 8 lanes; 6 samples per group per iter.
// COALESCED lane mapping: lane l8 owns floats [l8*4, l8*4+4) and [32+l8*4, ...):
// each LDG.128 covers exactly one 128B line per K row (halves L1TEX wavefronts
// vs the old interleaved l8*8 mapping — m was wavefront-bound).
__global__ __launch_bounds__(256) void m_kernel(const float* __restrict__ Q,
                                                const float* __restrict__ K) {
    __shared__ int sidx[8][UP];
    int warp = threadIdx.x >> 5;
    int lane = threadIdx.x & 31;
    int w  = blockIdx.x * 8 + warp;
    int bh = w >> 12;
    int q  = w & 4095;
    int b = bh >> 3, h = bh & 7;
    int g = lane >> 3, l8 = lane & 7;

    // recompute the 45 sample indices for this q (ALU idle; memory-bound kernel)
    sidx[warp][lane] = sample_idx(q, lane < UU ? lane : 0);
    if (lane < UU - 32) sidx[warp][lane + 32] = sample_idx(q, lane + 32);
    __syncwarp();

    const float* qp = Q + ((size_t)(b * LL + q) * HH + h) * DD + l8 * 4;
    float4 qa = *(const float4*)qp;
    float4 qb = *(const float4*)(qp + 32);
    const float* kbase = K + ((size_t)(b * LL) * HH + h) * DD + l8 * 4;
    const int* idxp = sidx[warp];

    float mx = -3.4e38f, sm = 0.f;
    // 2 iters x 4 groups x 6 samples = 48 slots >= 45
#pragma unroll 1
    for (int t = 0; t < 2; ++t) {
        float4 ka[6], kb[6];
        bool vv[6];
        // batch all 12 loads first (max MLP before any dependent compute)
#pragma unroll
        for (int k = 0; k < 6; ++k) {
            int s = t * 24 + k * 4 + g;
            vv[k] = (s < UU);
            int i = idxp[vv[k] ? s : 0];
            const float* kp = kbase + (size_t)i * (HH * DD);
            ka[k] = *(const float4*)kp;          // line 0 of the row
            kb[k] = *(const float4*)(kp + 32);   // line 1 of the row
        }
        float p[6];
#pragma unroll
        for (int k = 0; k < 6; ++k)
            p[k] = qa.x * ka[k].x + qa.y * ka[k].y + qa.z * ka[k].z + qa.w * ka[k].w
                 + qb.x * kb[k].x + qb.y * kb[k].y + qb.z * kb[k].z + qb.w * kb[k].w;
#pragma unroll
        for (int k = 0; k < 6; ++k) p[k] += __shfl_xor_sync(0xffffffffu, p[k], 1);
#pragma unroll
        for (int k = 0; k < 6; ++k) p[k] += __shfl_xor_sync(0xffffffffu, p[k], 2);
#pragma unroll
        for (int k = 0; k < 6; ++k) p[k] += __shfl_xor_sync(0xffffffffu, p[k], 4);
#pragma unroll
        for (int k = 0; k < 6; ++k)
            if (vv[k]) { mx = fmaxf(mx, p[k]); sm += p[k]; }
    }
    mx = fmaxf(mx, __shfl_xor_sync(0xffffffffu, mx, 8));
    sm +=           __shfl_xor_sync(0xffffffffu, sm, 8);
    mx = fmaxf(mx, __shfl_xor_sync(0xffffffffu, mx, 16));
    sm +=           __shfl_xor_sync(0xffffffffu, sm, 16);
    if (lane == 0) g_M[bh * LL + q] = mx - sm * (1.0f / LL);
}

// ---------------------------------------------------------------- top-45 via radix select + rank sort
// 1024 threads per (b,h). key = (ord(float) << 12) | (4095 - q): unique, value-desc / index-asc.
__global__ __launch_bounds__(1024) void topk_kernel() {
    __shared__ int hist[4096];
    __shared__ int wsum[32];
    __shared__ unsigned long long candk[CANDCAP];
    __shared__ int s_bin, s_nhi, s_cnt, s_bin2;
    int bh = blockIdx.x;
    int t = threadIdx.x;
    int lane = t & 31, warp = t >> 5;

    uint32_t u[4];
#pragma unroll
    for (int j = 0; j < 4; ++j) {
        uint32_t bits = __float_as_uint(g_M[bh * LL + t * 4 + j]);
        u[j] = (bits & 0x80000000u) ? ~bits : (bits | 0x80000000u);
    }
#pragma unroll
    for (int j = 0; j < 4; ++j) hist[t * 4 + j] = 0;
    if (t == 0) s_cnt = 0;
    __syncthreads();
#pragma unroll
    for (int j = 0; j < 4; ++j) atomicAdd(&hist[u[j] >> 20], 1);
    __syncthreads();

    {
        int h[4], c = 0;
#pragma unroll
        for (int j = 0; j < 4; ++j) { h[j] = hist[4095 - (t * 4 + j)]; c += h[j]; }
        int inc = c;
#pragma unroll
        for (int off = 1; off < 32; off <<= 1) {
            int v = __shfl_up_sync(0xffffffffu, inc, off);
            if (lane >= off) inc += v;
        }
        if (lane == 31) wsum[warp] = inc;
        __syncthreads();
        if (warp == 0) {
            int v = wsum[lane], iv = v;
#pragma unroll
            for (int off = 1; off < 32; off <<= 1) {
                int x = __shfl_up_sync(0xffffffffu, iv, off);
                if (lane >= off) iv += x;
            }
            wsum[lane] = iv - v;
        }
        __syncthreads();
        int run = wsum[warp] + (inc - c);
#pragma unroll
        for (int j = 0; j < 4; ++j) {
            int excl = run; run += h[j];
            if (excl < UU && run >= UU) { s_bin = 4095 - (t * 4 + j); s_nhi = excl; }
        }
    }
    __syncthreads();
    int B = s_bin;
    int nhi = s_nhi;
    int cntB = hist[B];
    bool lvl2 = (nhi + cntB > CANDCAP);

    unsigned long long key[4];
#pragma unroll
    for (int j = 0; j < 4; ++j)
        key[j] = ((unsigned long long)u[j] << 12) | (unsigned long long)(4095 - (t * 4 + j));

    if (!lvl2) {
#pragma unroll
        for (int j = 0; j < 4; ++j) {
            if ((int)(u[j] >> 20) >= B) {
                int pos = atomicAdd(&s_cnt, 1);
                if (pos < CANDCAP) candk[pos] = key[j];
            }
        }
    } else {
        __syncthreads();
#pragma unroll
        for (int j = 0; j < 4; ++j) hist[t * 4 + j] = 0;
        __syncthreads();
#pragma unroll
        for (int j = 0; j < 4; ++j)
            if ((int)(u[j] >> 20) == B) atomicAdd(&hist[(u[j] >> 8) & 0xfff], 1);
        __syncthreads();
        int r2 = UU - nhi;
        {
            int h[4], c = 0;
#pragma unroll
            for (int j = 0; j < 4; ++j) { h[j] = hist[4095 - (t * 4 + j)]; c += h[j]; }
            int inc = c;
#pragma unroll
            for (int off = 1; off < 32; off <<= 1) {
                int v = __shfl_up_sync(0xffffffffu, inc, off);
                if (lane >= off) inc += v;
            }
            if (lane == 31) wsum[warp] = inc;
            __syncthreads();
            if (warp == 0) {
                int v = wsum[lane], iv = v;
#pragma unroll
                for (int off = 1; off < 32; off <<= 1) {
                    int x = __shfl_up_sync(0xffffffffu, iv, off);
                    if (lane >= off) iv += x;
                }
                wsum[lane] = iv - v;
            }
            __syncthreads();
            int run = wsum[warp] + (inc - c);
#pragma unroll
            for (int j = 0; j < 4; ++j) {
                int excl = run; run += h[j];
                if (excl < r2 && run >= r2) s_bin2 = 4095 - (t * 4 + j);
            }
        }
        __syncthreads();
        int B2 = s_bin2;
#pragma unroll
        for (int j = 0; j < 4; ++j) {
            int bin = (int)(u[j] >> 20);
            int sub = (int)((u[j] >> 8) & 0xfff);
            if (bin > B || (bin == B && sub >= B2)) {
                int pos = atomicAdd(&s_cnt, 1);
                if (pos < CANDCAP) candk[pos] = key[j];
            }
        }
    }
    __syncthreads();

    int n = s_cnt < CANDCAP ? s_cnt : CANDCAP;
    if (t < n) {
        unsigned long long my = candk[t];
        int rank = 0;
        for (int j = 0; j < n; ++j) rank += (candk[j] > my);
        if (rank < UU) g_Mtop[bh * UU + rank] = 4095 - (int)(my & 0xfffull);
    }
}

// ---------------------------------------------------------------- split-K flash attention (64-wide tile)
// 256 thr = 16x16; thread owns 3 u-rows x (4 keys | 4 dims). Dynamic smem.
// (round-15 winner: smem-staged 3-phase softmax)
#define ASTR 68
#define SM_QS 0
#define SM_KS (SM_QS + UP * ASTR)
#define SM_VS (SM_KS + TIL * ASTR)
#define SM_SS (SM_VS + TIL * ASTR)
#define SM_MA (SM_SS + UP * ASTR)
#define SM_LB (SM_MA + UP * 4)
#define SM_MM (SM_LB + UP * 4)
#define SM_ML (SM_MM + UP)
#define SM_AL (SM_ML + UP)
#define SM_TOT (SM_AL + UP)

__global__ __launch_bounds__(256) void attn_kernel(const float* __restrict__ Q,
                                                   const float* __restrict__ K,
                                                   const float* __restrict__ V,
                                                   const int*   __restrict__ amask) {
    extern __shared__ float sm_[];
    float* Qs = sm_ + SM_QS;
    float* Ks = sm_ + SM_KS;
    float* Vs = sm_ + SM_VS;
    float* Ss = sm_ + SM_SS;
    float* SmA = sm_ + SM_MA;
    float* SlB = sm_ + SM_LB;
    float* smm = sm_ + SM_MM;
    float* sml = sm_ + SM_ML;
    float* sma = sm_ + SM_AL;

    int bh = blockIdx.x / NSPLIT;
    int sp = blockIdx.x % NSPLIT;
    int b = bh >> 3, h = bh & 7;
    int t = threadIdx.x;
    int tx = t & 15, ty = t >> 4;
    int u0 = ty * 3;

    for (int i = t; i < UP * DD; i += 256) {
        int u = i >> 6, d = i & 63;
        float v = 0.f;
        if (u < UU) {
            int qi = g_Mtop[bh * UU + u];
            v = Q[((size_t)(b * LL + qi) * HH + h) * DD + d] * 0.125f;  // 1/sqrt(64)
        }
        Qs[u * ASTR + d] = v;
    }
    if (t < UP) { smm[t] = -1e30f; sml[t] = 0.f; }

    float4 acc[3];
    acc[0] = make_float4(0.f, 0.f, 0.f, 0.f);
    acc[1] = acc[0]; acc[2] = acc[0];
    __syncthreads();

    int j0base = sp * KPB;
#pragma unroll 1
    for (int tile = 0; tile < NTILE; ++tile) {
        int j0 = j0base + tile * TIL;
        {
            const float* kb = K + ((size_t)(b * LL + j0) * HH + h) * DD;
            const float* vb = V + ((size_t)(b * LL + j0) * HH + h) * DD;
#pragma unroll
            for (int r = 0; r < 4; ++r) {
                int idx = t + 256 * r;
                int j = idx >> 4, c4 = idx & 15;
                *(float4*)&Ks[j * ASTR + c4 * 4] = *(const float4*)(kb + (size_t)j * (HH * DD) + c4 * 4);
                *(float4*)&Vs[j * ASTR + c4 * 4] = *(const float4*)(vb + (size_t)j * (HH * DD) + c4 * 4);
            }
        }
        __syncthreads();

        float s[3][4] = {};
#pragma unroll
        for (int d4 = 0; d4 < 16; ++d4) {
            float4 kv[4];
#pragma unroll
            for (int jj = 0; jj < 4; ++jj)
                kv[jj] = *(const float4*)&Ks[(tx + 16 * jj) * ASTR + d4 * 4];
#pragma unroll
            for (int uu = 0; uu < 3; ++uu) {
                float4 qv = *(const float4*)&Qs[(u0 + uu) * ASTR + d4 * 4];
#pragma unroll
                for (int jj = 0; jj < 4; ++jj)
                    s[uu][jj] += qv.x * kv[jj].x + qv.y * kv[jj].y
                               + qv.z * kv[jj].z + qv.w * kv[jj].w;
            }
        }
#pragma unroll
        for (int jj = 0; jj < 4; ++jj) {
            int jl = tx + 16 * jj;
            int mk = amask[b * LL + j0 + jl];
#pragma unroll
            for (int uu = 0; uu < 3; ++uu)
                Ss[(u0 + uu) * ASTR + jl] = mk ? s[uu][jj] : -1e30f;
        }
        __syncthreads();

        if (t < 192) {
            int u = t >> 2, c = t & 3;
            float cm = -1e30f;
#pragma unroll
            for (int j = 0; j < 16; ++j) cm = fmaxf(cm, Ss[u * ASTR + c * 16 + j]);
            SmA[u * 4 + c] = cm;
        }
        __syncthreads();
        if (t < 192) {
            int u = t >> 2, c = t & 3;
            float mnew = fmaxf(fmaxf(fmaxf(SmA[u * 4], SmA[u * 4 + 1]),
                                     fmaxf(SmA[u * 4 + 2], SmA[u * 4 + 3])), smm[u]);
            float ls = 0.f;
#pragma unroll
            for (int j = 0; j < 16; ++j) {
                float e = __expf(Ss[u * ASTR + c * 16 + j] - mnew);
                Ss[u * ASTR + c * 16 + j] = e;
                ls += e;
            }
            SlB[u * 4 + c] = ls;
        }
        __syncthreads();
        if (t < UP) {
            float mold = smm[t];
            float mnew = fmaxf(fmaxf(fmaxf(SmA[t * 4], SmA[t * 4 + 1]),
                                     fmaxf(SmA[t * 4 + 2], SmA[t * 4 + 3])), mold);
            float alpha = __expf(mold - mnew);
            sml[t] = sml[t] * alpha + SlB[t * 4] + SlB[t * 4 + 1] + SlB[t * 4 + 2] + SlB[t * 4 + 3];
            smm[t] = mnew;
            sma[t] = alpha;
        }
        __syncthreads();

#pragma unroll
        for (int uu = 0; uu < 3; ++uu) {
            float a = sma[u0 + uu];
            acc[uu].x *= a; acc[uu].y *= a; acc[uu].z *= a; acc[uu].w *= a;
        }
#pragma unroll
        for (int j4 = 0; j4 < TIL / 4; ++j4) {
            float4 vr0 = *(const float4*)&Vs[(j4 * 4 + 0) * ASTR + tx * 4];
            float4 vr1 = *(const float4*)&Vs[(j4 * 4 + 1) * ASTR + tx * 4];
            float4 vr2 = *(const float4*)&Vs[(j4 * 4 + 2) * ASTR + tx * 4];
            float4 vr3 = *(const float4*)&Vs[(j4 * 4 + 3) * ASTR + tx * 4];
#pragma unroll
            for (int uu = 0; uu < 3; ++uu) {
                float4 sv = *(const float4*)&Ss[(u0 + uu) * ASTR + j4 * 4];
                acc[uu].x += sv.x * vr0.x + sv.y * vr1.x + sv.z * vr2.x + sv.w * vr3.x;
                acc[uu].y += sv.x * vr0.y + sv.y * vr1.y + sv.z * vr2.y + sv.w * vr3.y;
                acc[uu].z += sv.x * vr0.z + sv.y * vr1.z + sv.z * vr2.z + sv.w * vr3.z;
                acc[uu].w += sv.x * vr0.w + sv.y * vr1.w + sv.z * vr2.w + sv.w * vr3.w;
            }
        }
        __syncthreads();
    }

    size_t base = (size_t)(bh * NSPLIT + sp) * UP;
#pragma unroll
    for (int uu = 0; uu < 3; ++uu)
        *(float4*)&g_pacc[(base + u0 + uu) * DD + tx * 4] = acc[uu];
    if (t < UP) { g_pm[base + t] = smm[t]; g_pl[base + t] = sml[t]; }
}

// ---------------------------------------------------------------- combine split-K partials
// block per (bh,u): 8 warps x 4 splits each, smem tree reduce.
__global__ __launch_bounds__(256) void combine_kernel(float* __restrict__ out) {
    __shared__ float s_wgt[NSPLIT];
    __shared__ float s_acc[8][DD];
    __shared__ float s_inv;
    int bh = blockIdx.x / UU, u = blockIdx.x % UU;
    int b = bh >> 3, h = bh & 7;
    int t = threadIdx.x;
    int warp = t >> 5, lane = t & 31;

    if (t < NSPLIT) s_wgt[t] = g_pm[(bh * NSPLIT + t) * UP + u];
    __syncthreads();

    if (warp == 0) {
        float mv = s_wgt[lane];
        float m = mv;
#pragma unroll
        for (int off = 16; off > 0; off >>= 1) m = fmaxf(m, __shfl_xor_sync(0xffffffffu, m, off));
        float wgt = __expf(mv - m);
        float ls = g_pl[(bh * NSPLIT + lane) * UP + u] * wgt;
#pragma unroll
        for (int off = 16; off > 0; off >>= 1) ls += __shfl_xor_sync(0xffffffffu, ls, off);
        s_wgt[lane] = wgt;
        if (lane == 0) s_inv = 1.0f / ls;
    }
    __syncthreads();

    float o0 = 0.f, o1 = 0.f;
#pragma unroll
    for (int k = 0; k < NSPLIT / 8; ++k) {
        int sp = warp * (NSPLIT / 8) + k;
        size_t pb = ((size_t)(bh * NSPLIT + sp) * UP + u) * DD;
        float wgt = s_wgt[sp];
        o0 += g_pacc[pb + lane] * wgt;
        o1 += g_pacc[pb + lane + 32] * wgt;
    }
    s_acc[warp][lane] = o0;
    s_acc[warp][lane + 32] = o1;
    __syncthreads();

    if (t < DD) {
        float s = 0.f;
#pragma unroll
        for (int w8 = 0; w8 < 8; ++w8) s += s_acc[w8][t];
        size_t ob = ((size_t)(b * UU + u) * HH + h) * DD;
        out[ob + t] = s * s_inv;
    }
}

// ----------------------------------------------------------------
extern "C" void kernel_launch(void* const* d_in, const int* in_sizes, int n_in,
                              void* d_out, int out_size) {
    const float* Q    = (const float*)d_in[0];
    const float* K    = (const float*)d_in[1];
    const float* V    = (const float*)d_in[2];
    const int*   mask = (const int*)d_in[3];
    float* out = (float*)d_out;

    const int attn_smem = SM_TOT * 4;
    cudaFuncSetAttribute(attn_kernel, cudaFuncAttributeMaxDynamicSharedMemorySize, attn_smem);

    m_kernel<<<NBH * LL / 8, 256>>>(Q, K);
    topk_kernel<<<NBH, 1024>>>();
    attn_kernel<<<NBH * NSPLIT, 256, attn_smem>>>(Q, K, V, mask);
    combine_kernel<<<NBH * UU, 256>>>(out);
}